// round 3
// baseline (speedup 1.0000x reference)
#include <cuda_runtime.h>

#define GN        128
#define GMASK     127
#define NCELLS    (GN * GN * GN)        // 2,097,152
#define NPTS_MAX  1000000

// low-level scan config: 512 blocks x 256 threads x 16 items = 2,097,152
#define SCAN_TPB   256
#define SCAN_ITEMS 16
#define SCAN_NBLK  512
#define SCAN_BLOCK_ITEMS (SCAN_TPB * SCAN_ITEMS)   // 4096

// ---- scratch (static device arrays; no allocation allowed) ----
__device__ unsigned g_counts[NCELLS];            // 8 MB  (destroyed by scatter)
__device__ unsigned g_cellStart[NCELLS + 1];     // 8 MB
__device__ unsigned g_partials[SCAN_NBLK];
__device__ float4   g_possorted[NPTS_MAX];       // 16 MB {rx, ry, rz, bitcast(orig idx)}
__device__ float4   g_grid[NCELLS * 2];          // 64 MB tiled layout [tile(4x4x4)][node][8 f32]

// tiled cell/node id: 4x4x4 tiles; 2KB contiguous per tile in g_grid
__device__ __forceinline__ int tiled_id(int x, int y, int z) {
    return ((((x >> 2) << 10) | ((y >> 2) << 5) | (z >> 2)) << 6)
         | (((x & 3) << 4) | ((y & 3) << 2) | (z & 3));
}

// ---------------- histogram ----------------
__global__ __launch_bounds__(256)
void hist_kernel(const float* __restrict__ pos, int n) {
    int i = blockIdx.x * blockDim.x + threadIdx.x;
    if (i >= n) return;
    int bx = (int)(pos[3 * i + 0] * (float)GN);
    int by = (int)(pos[3 * i + 1] * (float)GN);
    int bz = (int)(pos[3 * i + 2] * (float)GN);
    atomicAdd(&g_counts[tiled_id(bx, by, bz)], 1u);
}

// ---------------- scan ----------------
__device__ __forceinline__ unsigned blk_excl_scan_256(unsigned v, unsigned* swarp) {
    int lane = threadIdx.x & 31, wid = threadIdx.x >> 5;
    unsigned inc = v;
    #pragma unroll
    for (int o = 1; o < 32; o <<= 1) {
        unsigned t = __shfl_up_sync(0xffffffffu, inc, o);
        if (lane >= o) inc += t;
    }
    if (lane == 31) swarp[wid] = inc;
    __syncthreads();
    if (wid == 0) {
        unsigned w = (lane < 8) ? swarp[lane] : 0;
        #pragma unroll
        for (int o = 1; o < 8; o <<= 1) {
            unsigned t = __shfl_up_sync(0xffffffffu, w, o);
            if (lane >= o) w += t;
        }
        if (lane < 8) swarp[lane] = w;
    }
    __syncthreads();
    unsigned warp_off = wid ? swarp[wid - 1] : 0;
    return warp_off + inc - v;
}

// pass A: per-block sums of 4096 counts
__global__ __launch_bounds__(SCAN_TPB)
void scan_sums_kernel() {
    __shared__ unsigned ssum[8];
    const uint4* c4 = (const uint4*)g_counts;
    int base = blockIdx.x * (SCAN_BLOCK_ITEMS / 4) + threadIdx.x * (SCAN_ITEMS / 4);
    unsigned s = 0;
    #pragma unroll
    for (int k = 0; k < SCAN_ITEMS / 4; k++) {
        uint4 v = c4[base + k];
        s += v.x + v.y + v.z + v.w;
    }
    #pragma unroll
    for (int o = 16; o; o >>= 1) s += __shfl_down_sync(0xffffffffu, s, o);
    if ((threadIdx.x & 31) == 0) ssum[threadIdx.x >> 5] = s;
    __syncthreads();
    if (threadIdx.x == 0) {
        unsigned t = 0;
        #pragma unroll
        for (int w = 0; w < 8; w++) t += ssum[w];
        g_partials[blockIdx.x] = t;
    }
}

// pass B: exclusive scan of 512 partials (single block)
__global__ __launch_bounds__(SCAN_TPB)
void scan_top_kernel(int n) {
    __shared__ unsigned swarp[8];
    int base = threadIdx.x * 2;
    unsigned v0 = g_partials[base], v1 = g_partials[base + 1];
    unsigned excl = blk_excl_scan_256(v0 + v1, swarp);
    g_partials[base] = excl;
    g_partials[base + 1] = excl + v0;
    if (threadIdx.x == 0) g_cellStart[NCELLS] = (unsigned)n;
}

// pass C: per-block exclusive scan + global offset -> cellStart
__global__ __launch_bounds__(SCAN_TPB)
void scan_low_kernel() {
    __shared__ unsigned swarp[8];
    const uint4* c4 = (const uint4*)g_counts;
    uint4* o4 = (uint4*)g_cellStart;
    int base = blockIdx.x * (SCAN_BLOCK_ITEMS / 4) + threadIdx.x * (SCAN_ITEMS / 4);
    uint4 v[SCAN_ITEMS / 4];
    unsigned local = 0;
    #pragma unroll
    for (int k = 0; k < SCAN_ITEMS / 4; k++) {
        v[k] = c4[base + k];
        local += v[k].x + v[k].y + v[k].z + v[k].w;
    }
    unsigned excl = blk_excl_scan_256(local, swarp);
    unsigned off = g_partials[blockIdx.x] + excl;
    #pragma unroll
    for (int k = 0; k < SCAN_ITEMS / 4; k++) {
        uint4 w;
        w.x = off;            off += v[k].x;
        w.y = off;            off += v[k].y;
        w.z = off;            off += v[k].z;
        w.w = off;            off += v[k].w;
        o4[base + k] = w;
    }
}

// ---------------- scatter: reorder (rel coords + idx) into cell order ----------------
__global__ __launch_bounds__(256)
void scatter_kernel(const float* __restrict__ pos, int n) {
    int i = blockIdx.x * blockDim.x + threadIdx.x;
    if (i >= n) return;
    float rx = pos[3 * i + 0] * (float)GN;
    float ry = pos[3 * i + 1] * (float)GN;
    float rz = pos[3 * i + 2] * (float)GN;
    int cid = tiled_id((int)rx, (int)ry, (int)rz);
    unsigned k = atomicSub(&g_counts[cid], 1u);
    unsigned dst = g_cellStart[cid] + k - 1;
    g_possorted[dst] = make_float4(rx, ry, rz, __int_as_float(i));
}

// ---------------- P2G: sorted scatter-add, coalesced-ish RED.128 ----------------
__global__ __launch_bounds__(256)
void p2g_kernel(const float4* __restrict__ feat4, int n) {
    int i = blockIdx.x * blockDim.x + threadIdx.x;
    if (i >= n) return;
    float4 pp = g_possorted[i];
    int bx = (int)pp.x, by = (int)pp.y, bz = (int)pp.z;
    float fx = pp.x - (float)bx, fy = pp.y - (float)by, fz = pp.z - (float)bz;
    int orig = __float_as_int(pp.w);

    float4 f0 = __ldg(&feat4[2 * orig + 0]);
    float4 f1 = __ldg(&feat4[2 * orig + 1]);

    float wxa[2] = {1.f - fx, fx};
    float wya[2] = {1.f - fy, fy};
    float wza[2] = {1.f - fz, fz};

    #pragma unroll
    for (int ox = 0; ox < 2; ox++) {
        int nx = (bx + ox) & GMASK;
        #pragma unroll
        for (int oy = 0; oy < 2; oy++) {
            int ny = (by + oy) & GMASK;
            float wxy = wxa[ox] * wya[oy];
            #pragma unroll
            for (int oz = 0; oz < 2; oz++) {
                int nz = (bz + oz) & GMASK;
                float w = wxy * wza[oz];
                int nid = tiled_id(nx, ny, nz);
                float4 c0 = make_float4(w * f0.x, w * f0.y, w * f0.z, w * f0.w);
                float4 c1 = make_float4(w * f1.x, w * f1.y, w * f1.z, w * f1.w);
                atomicAdd(&g_grid[2 * nid + 0], c0);
                atomicAdd(&g_grid[2 * nid + 1], c1);
            }
        }
    }
}

// ---------------- G2P: sorted gather, tiled grid -> few lines per warp ----------------
__global__ __launch_bounds__(256)
void g2p_kernel(float4* __restrict__ out4, int n) {
    int i = blockIdx.x * blockDim.x + threadIdx.x;
    if (i >= n) return;
    float4 pp = g_possorted[i];
    int bx = (int)pp.x, by = (int)pp.y, bz = (int)pp.z;
    float fx = pp.x - (float)bx, fy = pp.y - (float)by, fz = pp.z - (float)bz;

    float wxa[2] = {1.f - fx, fx};
    float wya[2] = {1.f - fy, fy};
    float wza[2] = {1.f - fz, fz};

    float4 acc0 = make_float4(0.f, 0.f, 0.f, 0.f);
    float4 acc1 = make_float4(0.f, 0.f, 0.f, 0.f);

    #pragma unroll
    for (int ox = 0; ox < 2; ox++) {
        int nx = (bx + ox) & GMASK;
        #pragma unroll
        for (int oy = 0; oy < 2; oy++) {
            int ny = (by + oy) & GMASK;
            float wxy = wxa[ox] * wya[oy];
            #pragma unroll
            for (int oz = 0; oz < 2; oz++) {
                int nz = (bz + oz) & GMASK;
                float w = wxy * wza[oz];
                int nid = tiled_id(nx, ny, nz);
                float4 g0 = __ldg(&g_grid[2 * nid + 0]);
                float4 g1 = __ldg(&g_grid[2 * nid + 1]);
                acc0.x += w * g0.x; acc0.y += w * g0.y;
                acc0.z += w * g0.z; acc0.w += w * g0.w;
                acc1.x += w * g1.x; acc1.y += w * g1.y;
                acc1.z += w * g1.z; acc1.w += w * g1.w;
            }
        }
    }
    int orig = __float_as_int(pp.w);
    out4[2 * orig + 0] = acc0;
    out4[2 * orig + 1] = acc1;
}

extern "C" void kernel_launch(void* const* d_in, const int* in_sizes, int n_in,
                              void* d_out, int out_size) {
    const float* pos  = (const float*)d_in[0];   // [N,3] f32
    const float* feat = (const float*)d_in[1];   // [N,8] f32
    float* out        = (float*)d_out;           // [N,8] f32
    int n = in_sizes[0] / 3;

    void* cptr = nullptr;
    cudaGetSymbolAddress(&cptr, g_counts);
    cudaMemsetAsync(cptr, 0, (size_t)NCELLS * sizeof(unsigned), 0);
    void* gptr = nullptr;
    cudaGetSymbolAddress(&gptr, g_grid);
    cudaMemsetAsync(gptr, 0, (size_t)NCELLS * 2 * sizeof(float4), 0);

    int tpb = 256;
    int pblocks = (n + tpb - 1) / tpb;

    hist_kernel<<<pblocks, tpb>>>(pos, n);
    scan_sums_kernel<<<SCAN_NBLK, SCAN_TPB>>>();
    scan_top_kernel<<<1, SCAN_TPB>>>(n);
    scan_low_kernel<<<SCAN_NBLK, SCAN_TPB>>>();
    scatter_kernel<<<pblocks, tpb>>>(pos, n);
    p2g_kernel<<<pblocks, tpb>>>((const float4*)feat, n);
    g2p_kernel<<<pblocks, tpb>>>((float4*)out, n);
}

// round 4
// speedup vs baseline: 1.1523x; 1.1523x over previous
#include <cuda_runtime.h>

#define GN     128
#define GMASK  127
#define NCELLS (GN * GN * GN)

// grid scratch: [cell][2 float4] = 64 MB, plain z-major
__device__ float4 g_grid[NCELLS * 2];

// 16 lanes per point, 2 points per warp.
// lane layout: sub = lane>>4 (which point), k = lane&15, node = k>>1 (0..7), half = k&1.
__global__ __launch_bounds__(256)
void p2g_coop(const float* __restrict__ pos,
              const float4* __restrict__ feat4, int n) {
    int lane = threadIdx.x & 31;
    int warp = (blockIdx.x * blockDim.x + threadIdx.x) >> 5;
    int i = warp * 2 + (lane >> 4);
    if (i >= n) return;

    int k = lane & 15;
    int node = k >> 1;
    int half = k & 1;
    int ox = node >> 2, oy = (node >> 1) & 1, oz = node & 1;

    float rx = __ldg(&pos[3 * i + 0]) * (float)GN;
    float ry = __ldg(&pos[3 * i + 1]) * (float)GN;
    float rz = __ldg(&pos[3 * i + 2]) * (float)GN;
    int bx = (int)rx, by = (int)ry, bz = (int)rz;
    float fx = rx - (float)bx, fy = ry - (float)by, fz = rz - (float)bz;

    float w = (ox ? fx : 1.0f - fx) * (oy ? fy : 1.0f - fy) * (oz ? fz : 1.0f - fz);

    float4 f = __ldg(&feat4[2 * i + half]);

    int nx = (bx + ox) & GMASK;
    int ny = (by + oy) & GMASK;
    int nz = (bz + oz) & GMASK;
    int nid = ((nx << 7 | ny) << 7) | nz;

    float4 c = make_float4(w * f.x, w * f.y, w * f.z, w * f.w);
    atomicAdd(&g_grid[2 * nid + half], c);
}

__global__ __launch_bounds__(256)
void g2p_coop(const float* __restrict__ pos,
              float4* __restrict__ out4, int n) {
    int lane = threadIdx.x & 31;
    int warp = (blockIdx.x * blockDim.x + threadIdx.x) >> 5;
    int i = warp * 2 + (lane >> 4);
    bool active = (i < n);
    int ic = active ? i : (n - 1);   // keep all lanes resident for shuffles

    int k = lane & 15;
    int node = k >> 1;
    int half = k & 1;
    int ox = node >> 2, oy = (node >> 1) & 1, oz = node & 1;

    float rx = __ldg(&pos[3 * ic + 0]) * (float)GN;
    float ry = __ldg(&pos[3 * ic + 1]) * (float)GN;
    float rz = __ldg(&pos[3 * ic + 2]) * (float)GN;
    int bx = (int)rx, by = (int)ry, bz = (int)rz;
    float fx = rx - (float)bx, fy = ry - (float)by, fz = rz - (float)bz;

    float w = (ox ? fx : 1.0f - fx) * (oy ? fy : 1.0f - fy) * (oz ? fz : 1.0f - fz);

    int nx = (bx + ox) & GMASK;
    int ny = (by + oy) & GMASK;
    int nz = (bz + oz) & GMASK;
    int nid = ((nx << 7 | ny) << 7) | nz;

    float4 g = __ldg(&g_grid[2 * nid + half]);
    float4 v = make_float4(w * g.x, w * g.y, w * g.z, w * g.w);

    // reduce over node index = lane bits 1..3 (butterfly xor 2,4,8); bit0(half) and bit4(sub) preserved
    #pragma unroll
    for (int m = 2; m <= 8; m <<= 1) {
        v.x += __shfl_xor_sync(0xffffffffu, v.x, m);
        v.y += __shfl_xor_sync(0xffffffffu, v.y, m);
        v.z += __shfl_xor_sync(0xffffffffu, v.z, m);
        v.w += __shfl_xor_sync(0xffffffffu, v.w, m);
    }

    if (active && k < 2) {
        out4[2 * i + half] = v;   // lanes 0,1,16,17 -> 64B contiguous per warp
    }
}

extern "C" void kernel_launch(void* const* d_in, const int* in_sizes, int n_in,
                              void* d_out, int out_size) {
    const float* pos  = (const float*)d_in[0];   // [N,3] f32
    const float* feat = (const float*)d_in[1];   // [N,8] f32
    float* out        = (float*)d_out;           // [N,8] f32
    int n = in_sizes[0] / 3;

    void* gptr = nullptr;
    cudaGetSymbolAddress(&gptr, g_grid);
    cudaMemsetAsync(gptr, 0, (size_t)NCELLS * 2 * sizeof(float4), 0);

    // 16 lanes per point: 16 points per 256-thread block
    int blocks = (n + 15) / 16;
    p2g_coop<<<blocks, 256>>>(pos, (const float4*)feat, n);
    g2p_coop<<<blocks, 256>>>(pos, (float4*)out, n);
}

// round 5
// speedup vs baseline: 1.3919x; 1.2080x over previous
#include <cuda_runtime.h>

#define GN     128
#define GMASK  127
#define NCELLS (GN * GN * GN)

// grid scratch: [cell][2 float4] = 64 MB, plain z-major
__device__ float4 g_grid[NCELLS * 2];

// ---------------- P2G: 16 lanes/point, 2 points/warp (measured ~60us, keep) ----------------
// lane layout: sub = lane>>4 (which point), k = lane&15, node = k>>1 (0..7), half = k&1.
__global__ __launch_bounds__(256)
void p2g_coop(const float* __restrict__ pos,
              const float4* __restrict__ feat4, int n) {
    int lane = threadIdx.x & 31;
    int warp = (blockIdx.x * blockDim.x + threadIdx.x) >> 5;
    int i = warp * 2 + (lane >> 4);
    if (i >= n) return;

    int k = lane & 15;
    int node = k >> 1;
    int half = k & 1;
    int ox = node >> 2, oy = (node >> 1) & 1, oz = node & 1;

    float rx = __ldg(&pos[3 * i + 0]) * (float)GN;
    float ry = __ldg(&pos[3 * i + 1]) * (float)GN;
    float rz = __ldg(&pos[3 * i + 2]) * (float)GN;
    int bx = (int)rx, by = (int)ry, bz = (int)rz;
    float fx = rx - (float)bx, fy = ry - (float)by, fz = rz - (float)bz;

    float w = (ox ? fx : 1.0f - fx) * (oy ? fy : 1.0f - fy) * (oz ? fz : 1.0f - fz);

    float4 f = __ldg(&feat4[2 * i + half]);

    int nx = (bx + ox) & GMASK;
    int ny = (by + oy) & GMASK;
    int nz = (bz + oz) & GMASK;
    int nid = ((nx << 7 | ny) << 7) | nz;

    float4 c = make_float4(w * f.x, w * f.y, w * f.z, w * f.w);
    atomicAdd(&g_grid[2 * nid + half], c);
}

// ---------------- G2P: 8 lanes/point, 4 points/warp, halving-exchange reduce ----------------
// lane = p*8 + j;  p = point sub-index (0..3), j = stencil node (0..7).
// After the butterfly, lane p*8+j holds output component j of point p,
// so the store is out[warp*32 + lane] — perfectly coalesced.
__global__ __launch_bounds__(256)
void g2p_coop8(const float* __restrict__ pos,
               float* __restrict__ out, int n) {
    int lane = threadIdx.x & 31;
    int warp = (blockIdx.x * blockDim.x + threadIdx.x) >> 5;
    int p = lane >> 3;
    int j = lane & 7;
    int i = warp * 4 + p;
    bool active = (i < n);
    int ic = active ? i : (n - 1);   // keep all lanes resident for shuffles

    int ox = j >> 2, oy = (j >> 1) & 1, oz = j & 1;

    float rx = __ldg(&pos[3 * ic + 0]) * (float)GN;
    float ry = __ldg(&pos[3 * ic + 1]) * (float)GN;
    float rz = __ldg(&pos[3 * ic + 2]) * (float)GN;
    int bx = (int)rx, by = (int)ry, bz = (int)rz;
    float fx = rx - (float)bx, fy = ry - (float)by, fz = rz - (float)bz;

    float w = (ox ? fx : 1.0f - fx) * (oy ? fy : 1.0f - fy) * (oz ? fz : 1.0f - fz);

    int nx = (bx + ox) & GMASK;
    int ny = (by + oy) & GMASK;
    int nz = (bz + oz) & GMASK;
    int nid = ((nx << 7 | ny) << 7) | nz;

    // 32B node record: both halves live in the same 128B line.
    float4 g0 = __ldg(&g_grid[2 * nid + 0]);
    float4 g1 = __ldg(&g_grid[2 * nid + 1]);

    float v0 = w * g0.x, v1 = w * g0.y, v2 = w * g0.z, v3 = w * g0.w;
    float v4 = w * g1.x, v5 = w * g1.y, v6 = w * g1.z, v7 = w * g1.w;

    // Halving-exchange butterfly over node bits of the lane id.
    // Level m=4: keep comps whose bit2 matches j's bit2; 4 SHFL.
    bool j4 = (j & 4) != 0;
    bool j2 = (j & 2) != 0;
    bool j1 = (j & 1) != 0;

    float a0, a1, a2, a3, s;
    s = j4 ? v0 : v4;  a0 = (j4 ? v4 : v0) + __shfl_xor_sync(0xffffffffu, s, 4);
    s = j4 ? v1 : v5;  a1 = (j4 ? v5 : v1) + __shfl_xor_sync(0xffffffffu, s, 4);
    s = j4 ? v2 : v6;  a2 = (j4 ? v6 : v2) + __shfl_xor_sync(0xffffffffu, s, 4);
    s = j4 ? v3 : v7;  a3 = (j4 ? v7 : v3) + __shfl_xor_sync(0xffffffffu, s, 4);

    // Level m=2: a{0,1} hold comps (j&4)+{0,1} after this; 2 SHFL.
    float b0, b1;
    s = j2 ? a0 : a2;  b0 = (j2 ? a2 : a0) + __shfl_xor_sync(0xffffffffu, s, 2);
    s = j2 ? a1 : a3;  b1 = (j2 ? a3 : a1) + __shfl_xor_sync(0xffffffffu, s, 2);

    // Level m=1: final comp = j; 1 SHFL.
    s = j1 ? b0 : b1;
    float r = (j1 ? b1 : b0) + __shfl_xor_sync(0xffffffffu, s, 1);

    if (active) {
        out[(size_t)warp * 32 + lane] = r;   // == out[8*i + j], fully coalesced
    }
}

extern "C" void kernel_launch(void* const* d_in, const int* in_sizes, int n_in,
                              void* d_out, int out_size) {
    const float* pos  = (const float*)d_in[0];   // [N,3] f32
    const float* feat = (const float*)d_in[1];   // [N,8] f32
    float* out        = (float*)d_out;           // [N,8] f32
    int n = in_sizes[0] / 3;

    void* gptr = nullptr;
    cudaGetSymbolAddress(&gptr, g_grid);
    cudaMemsetAsync(gptr, 0, (size_t)NCELLS * 2 * sizeof(float4), 0);

    // p2g: 16 lanes/point -> 16 points per 256-thread block
    int pb = (n + 15) / 16;
    p2g_coop<<<pb, 256>>>(pos, (const float4*)feat, n);

    // g2p: 8 lanes/point -> 32 points per 256-thread block
    int gb = (n + 31) / 32;
    g2p_coop8<<<gb, 256>>>(pos, (float*)out, n);
}